// round 1
// baseline (speedup 1.0000x reference)
#include <cuda_runtime.h>

#define NB 32
#define NC 256
#define NHW 3136
#define NHW4 784          // 3136 / 4
#define NG 32
#define EPSV 1e-5f

// Scratch (no allocations allowed)
__device__ float d_pooled[NB * NC];
__device__ float d_scale[NB * NC];
__device__ float d_shift[NB * NC];

// ---------------------------------------------------------------------------
// Pass 1: per-(b,c) plane mean pool. One block per plane, coalesced float4.
// ---------------------------------------------------------------------------
__global__ void pool_kernel(const float* __restrict__ x) {
    const int plane = blockIdx.x;                        // b*NC + c
    const float4* __restrict__ xp =
        reinterpret_cast<const float4*>(x + (size_t)plane * NHW);

    float s = 0.0f;
    for (int i = threadIdx.x; i < NHW4; i += blockDim.x) {
        float4 v = xp[i];
        s += (v.x + v.y) + (v.z + v.w);
    }

    // block reduce
    __shared__ float sh[32];
    const int lane = threadIdx.x & 31;
    const int wid  = threadIdx.x >> 5;
    #pragma unroll
    for (int o = 16; o > 0; o >>= 1) s += __shfl_down_sync(0xffffffffu, s, o);
    if (lane == 0) sh[wid] = s;
    __syncthreads();
    if (wid == 0) {
        s = (lane < (blockDim.x >> 5)) ? sh[lane] : 0.0f;
        #pragma unroll
        for (int o = 16; o > 0; o >>= 1) s += __shfl_down_sync(0xffffffffu, s, o);
        if (lane == 0) d_pooled[plane] = s * (1.0f / (float)NHW);
    }
}

// ---------------------------------------------------------------------------
// Pass 2: per-channel coefficients + per-batch alpha + fused scale/shift.
// Single block, 256 threads (thread == channel).
// ---------------------------------------------------------------------------
__global__ void coef_kernel(const float* __restrict__ alpha_w,
                            const float* __restrict__ alpha_b,
                            const float* __restrict__ g_w,
                            const float* __restrict__ g_b,
                            const float* __restrict__ g_rm,
                            const float* __restrict__ g_rv,
                            const float* __restrict__ grp_w,
                            const float* __restrict__ grp_b,
                            const float* __restrict__ grp_rm,
                            const float* __restrict__ grp_rv) {
    const int c = threadIdx.x;   // 0..255

    // global-BN affine
    const float gs  = g_w[c] * rsqrtf(g_rv[c] + EPSV);
    const float gsh = g_b[c] - g_rm[c] * gs;

    // group-mean affine
    float ms = 0.0f, msh = 0.0f;
    #pragma unroll 4
    for (int g = 0; g < NG; g++) {
        const int idx = g * NC + c;
        const float sg = grp_w[idx] * rsqrtf(grp_rv[idx] + EPSV);
        ms  += sg;
        msh += grp_b[idx] - grp_rm[idx] * sg;
    }
    ms  *= (1.0f / (float)NG);
    msh *= (1.0f / (float)NG);

    // alpha per batch: threads 0..31 each do a 256-wide dot + sigmoid
    __shared__ float alpha_sh[NB];
    if (c < NB) {
        float acc = alpha_b[0];
        const float* __restrict__ pr = d_pooled + c * NC;
        #pragma unroll 8
        for (int k = 0; k < NC; k++) acc += pr[k] * alpha_w[k];
        alpha_sh[c] = 1.0f / (1.0f + expf(-acc));
    }
    __syncthreads();

    #pragma unroll 4
    for (int b = 0; b < NB; b++) {
        const float a  = alpha_sh[b];
        const float na = 1.0f - a;
        d_scale[b * NC + c] = na * gs  + a * ms;
        d_shift[b * NC + c] = na * gsh + a * msh;
    }
}

// ---------------------------------------------------------------------------
// Pass 3: out = x * scale[b,c] + shift[b,c]. One block per plane, float4.
// ---------------------------------------------------------------------------
__global__ void apply_kernel(const float* __restrict__ x,
                             float* __restrict__ out) {
    const int plane = blockIdx.x;
    const float sc = d_scale[plane];
    const float sf = d_shift[plane];

    const float4* __restrict__ xp =
        reinterpret_cast<const float4*>(x + (size_t)plane * NHW);
    float4* __restrict__ op =
        reinterpret_cast<float4*>(out + (size_t)plane * NHW);

    for (int i = threadIdx.x; i < NHW4; i += blockDim.x) {
        float4 v = xp[i];
        v.x = fmaf(v.x, sc, sf);
        v.y = fmaf(v.y, sc, sf);
        v.z = fmaf(v.z, sc, sf);
        v.w = fmaf(v.w, sc, sf);
        op[i] = v;
    }
}

extern "C" void kernel_launch(void* const* d_in, const int* in_sizes, int n_in,
                              void* d_out, int out_size) {
    const float* x       = (const float*)d_in[0];
    // d_in[1] = labels (unused by reference output)
    const float* alpha_w = (const float*)d_in[2];
    const float* alpha_b = (const float*)d_in[3];
    const float* g_w     = (const float*)d_in[4];
    const float* g_b     = (const float*)d_in[5];
    const float* g_rm    = (const float*)d_in[6];
    const float* g_rv    = (const float*)d_in[7];
    const float* grp_w   = (const float*)d_in[8];
    const float* grp_b   = (const float*)d_in[9];
    const float* grp_rm  = (const float*)d_in[10];
    const float* grp_rv  = (const float*)d_in[11];
    float* out = (float*)d_out;

    pool_kernel<<<NB * NC, 128>>>(x);
    coef_kernel<<<1, NC>>>(alpha_w, alpha_b, g_w, g_b, g_rm, g_rv,
                           grp_w, grp_b, grp_rm, grp_rv);
    apply_kernel<<<NB * NC, 256>>>(x, out);
}

// round 2
// speedup vs baseline: 1.1888x; 1.1888x over previous
#include <cuda_runtime.h>

#define NB 32
#define NC 256
#define NHW 3136
#define NHW4 784          // float4 per plane
#define NG 32
#define EPSV 1e-5f

#define TPB 224           // 7 warps; 2*784 / 224 = 7 exactly
#define PER_TH 7
#define NPAIR (NB * NC / 2)   // 4096 blocks, 2 planes each

__device__ float d_pooled[NB * NC];

// ---------------------------------------------------------------------------
// Pass 1: mean pool, 2 planes per block, 7 fully-unrolled float4 loads/thread.
// ---------------------------------------------------------------------------
__global__ __launch_bounds__(TPB) void pool_kernel(const float* __restrict__ x) {
    const int pair = blockIdx.x;
    const float4* __restrict__ xp =
        reinterpret_cast<const float4*>(x + (size_t)pair * 2 * NHW);

    // front-batched loads for MLP
    float4 v[PER_TH];
    #pragma unroll
    for (int k = 0; k < PER_TH; k++)
        v[k] = xp[threadIdx.x + k * TPB];

    float s0 = 0.0f, s1 = 0.0f;
    #pragma unroll
    for (int k = 0; k < PER_TH; k++) {
        const int j = threadIdx.x + k * TPB;
        const float t = (v[k].x + v[k].y) + (v[k].z + v[k].w);
        if (j < NHW4) s0 += t; else s1 += t;
    }

    __shared__ float sh0[8], sh1[8];
    const int lane = threadIdx.x & 31;
    const int wid  = threadIdx.x >> 5;
    #pragma unroll
    for (int o = 16; o > 0; o >>= 1) {
        s0 += __shfl_down_sync(0xffffffffu, s0, o);
        s1 += __shfl_down_sync(0xffffffffu, s1, o);
    }
    if (lane == 0) { sh0[wid] = s0; sh1[wid] = s1; }
    __syncthreads();
    if (threadIdx.x == 0) {
        float a = 0.0f, b = 0.0f;
        #pragma unroll
        for (int w = 0; w < 7; w++) { a += sh0[w]; b += sh1[w]; }
        d_pooled[pair * 2 + 0] = a * (1.0f / (float)NHW);
        d_pooled[pair * 2 + 1] = b * (1.0f / (float)NHW);
    }
}

// ---------------------------------------------------------------------------
// Pass 2: fused coefficients + apply. 2 planes per block.
//   warp 0 computes alpha (256-wide dot, L2 hits) + both channels' scale/shift.
//   Then 224 threads stream 1568 float4: read x (L2-resident), streaming store.
// ---------------------------------------------------------------------------
__global__ __launch_bounds__(TPB) void apply_kernel(
    const float* __restrict__ x, float* __restrict__ out,
    const float* __restrict__ alpha_w, const float* __restrict__ alpha_b,
    const float* __restrict__ g_w,  const float* __restrict__ g_b,
    const float* __restrict__ g_rm, const float* __restrict__ g_rv,
    const float* __restrict__ grp_w,  const float* __restrict__ grp_b,
    const float* __restrict__ grp_rm, const float* __restrict__ grp_rv) {

    const int pair   = blockIdx.x;
    const int plane0 = pair * 2;
    const int b      = plane0 >> 8;   // plane0 even -> both planes same batch
    const int c0     = plane0 & 255;

    __shared__ float s_sc[2], s_sh[2];

    if (threadIdx.x < 32) {
        const int lane = threadIdx.x;
        // alpha = sigmoid(pooled[b,:] . alpha_w + alpha_b)
        float acc = 0.0f;
        #pragma unroll
        for (int m = 0; m < 8; m++) {
            const int idx = lane + 32 * m;
            acc += d_pooled[b * NC + idx] * alpha_w[idx];
        }
        #pragma unroll
        for (int o = 16; o > 0; o >>= 1)
            acc += __shfl_xor_sync(0xffffffffu, acc, o);
        const float a = 1.0f / (1.0f + expf(-(acc + alpha_b[0])));

        if (lane < 2) {
            const int c = c0 + lane;
            const float gs  = g_w[c] * rsqrtf(g_rv[c] + EPSV);
            const float gsh = g_b[c] - g_rm[c] * gs;
            float ms = 0.0f, msh = 0.0f;
            #pragma unroll 8
            for (int g = 0; g < NG; g++) {
                const int idx = g * NC + c;
                const float sg = grp_w[idx] * rsqrtf(grp_rv[idx] + EPSV);
                ms  += sg;
                msh += grp_b[idx] - grp_rm[idx] * sg;
            }
            ms  *= (1.0f / (float)NG);
            msh *= (1.0f / (float)NG);
            s_sc[lane] = (1.0f - a) * gs  + a * ms;
            s_sh[lane] = (1.0f - a) * gsh + a * msh;
        }
    }
    __syncthreads();

    const float sc0 = s_sc[0], sf0 = s_sh[0];
    const float sc1 = s_sc[1], sf1 = s_sh[1];

    const float4* __restrict__ xp =
        reinterpret_cast<const float4*>(x + (size_t)plane0 * NHW);
    float4* __restrict__ op =
        reinterpret_cast<float4*>(out + (size_t)plane0 * NHW);

    float4 v[PER_TH];
    #pragma unroll
    for (int k = 0; k < PER_TH; k++)
        v[k] = xp[threadIdx.x + k * TPB];

    #pragma unroll
    for (int k = 0; k < PER_TH; k++) {
        const int j = threadIdx.x + k * TPB;
        const float sc = (j < NHW4) ? sc0 : sc1;
        const float sf = (j < NHW4) ? sf0 : sf1;
        float4 r;
        r.x = fmaf(v[k].x, sc, sf);
        r.y = fmaf(v[k].y, sc, sf);
        r.z = fmaf(v[k].z, sc, sf);
        r.w = fmaf(v[k].w, sc, sf);
        __stcs(&op[j], r);   // streaming store: don't evict x from L2
    }
}

extern "C" void kernel_launch(void* const* d_in, const int* in_sizes, int n_in,
                              void* d_out, int out_size) {
    const float* x       = (const float*)d_in[0];
    // d_in[1] = labels (unused)
    const float* alpha_w = (const float*)d_in[2];
    const float* alpha_b = (const float*)d_in[3];
    const float* g_w     = (const float*)d_in[4];
    const float* g_b     = (const float*)d_in[5];
    const float* g_rm    = (const float*)d_in[6];
    const float* g_rv    = (const float*)d_in[7];
    const float* grp_w   = (const float*)d_in[8];
    const float* grp_b   = (const float*)d_in[9];
    const float* grp_rm  = (const float*)d_in[10];
    const float* grp_rv  = (const float*)d_in[11];
    float* out = (float*)d_out;

    pool_kernel<<<NPAIR, TPB>>>(x);
    apply_kernel<<<NPAIR, TPB>>>(x, out,
                                 alpha_w, alpha_b,
                                 g_w, g_b, g_rm, g_rv,
                                 grp_w, grp_b, grp_rm, grp_rv);
}